// round 2
// baseline (speedup 1.0000x reference)
#include <cuda_runtime.h>

#define NN 50000
#define NE 1000000
#define NEP 400000
#define HD 128
#define CD 768

// ---------------- scratch (no allocation allowed) ----------------
static __device__ float g_bufA[NN * HD]; // h = z @ W
static __device__ float g_bufB[NN * HD]; // z (post-layer)
static __device__ float g_bufC[NN * HD]; // agg
static __device__ float g_bufD[NN * HD]; // c (chem features)
static __device__ float g_dinv[NN];
static __device__ int   g_deg[NN];

// ---------------- degree / dinv ----------------
__global__ void deg_kernel(const int* __restrict__ col) {
    int e = blockIdx.x * blockDim.x + threadIdx.x;
    if (e < NE) atomicAdd(&g_deg[col[e]], 1);
}

__global__ void dinv_kernel() {
    int n = blockIdx.x * blockDim.x + threadIdx.x;
    if (n < NN) {
        int d = g_deg[n];
        g_dinv[n] = d > 0 ? rsqrtf((float)d) : 0.0f;
    }
}

// ---------------- edge scatter: agg[col] += h[row] * norm ----------------
// one warp per edge; lane handles 4 contiguous features via float4 read
__global__ void scatter_kernel(const int* __restrict__ ei,
                               const float* __restrict__ h,
                               float* __restrict__ agg) {
    int gt = blockIdx.x * blockDim.x + threadIdx.x;
    int e = gt >> 5;
    int lane = gt & 31;
    if (e >= NE) return;
    int r = ei[e];
    int c = ei[NE + e];
    float nrm = g_dinv[r] * g_dinv[c];
    float4 v = reinterpret_cast<const float4*>(h)[r * 32 + lane];
    float* dst = agg + (size_t)c * HD + lane * 4;
    atomicAdd(dst + 0, v.x * nrm);
    atomicAdd(dst + 1, v.y * nrm);
    atomicAdd(dst + 2, v.z * nrm);
    atomicAdd(dst + 3, v.w * nrm);
}

// ---------------- z = relu(agg + b) ----------------
__global__ void bias_relu_kernel(const float* __restrict__ agg,
                                 const float* __restrict__ b,
                                 float* __restrict__ z) {
    int i = blockIdx.x * blockDim.x + threadIdx.x;
    if (i < NN * HD) z[i] = fmaxf(agg[i] + b[i & (HD - 1)], 0.0f);
}

// ---------------- tiled fp32 GEMM: out = op(A[M,K] @ W[K,128]) ----------------
// tile 128 rows x 128 cols, K chunked by 64. 256 threads, 16x4 per thread.
// MODE 0: raw store. MODE 1: relu(x + bias[col]) * mask[row]
template <int KTOT, int MODE>
__global__ void __launch_bounds__(256)
gemm128_kernel(const float* __restrict__ A,
               const float* __restrict__ W,
               const float* __restrict__ bias,
               const float* __restrict__ mask,
               float* __restrict__ out, int M) {
    extern __shared__ float sm[];
    float* As = sm;            // 128*64
    float* Ws = sm + 128 * 64; // 64*128
    int tid = threadIdx.x;
    int tx = tid & 31, ty = tid >> 5;
    int rowBase = blockIdx.x * 128;

    float acc[16][4];
#pragma unroll
    for (int ri = 0; ri < 16; ri++)
#pragma unroll
        for (int ci = 0; ci < 4; ci++) acc[ri][ci] = 0.0f;

    for (int kc = 0; kc < KTOT / 64; kc++) {
        // load A chunk [128][64]
#pragma unroll
        for (int i = 0; i < 8; i++) {
            int f4 = tid + 256 * i;       // 0..2047
            int r = f4 >> 4, kk = f4 & 15;
            int gr = rowBase + r;
            float4 v = make_float4(0.f, 0.f, 0.f, 0.f);
            if (gr < M)
                v = *reinterpret_cast<const float4*>(A + (size_t)gr * KTOT + kc * 64 + kk * 4);
            *reinterpret_cast<float4*>(As + r * 64 + kk * 4) = v;
        }
        // load W chunk [64][128]
#pragma unroll
        for (int i = 0; i < 8; i++) {
            int f4 = tid + 256 * i;
            int r = f4 >> 5, cc = f4 & 31;
            *reinterpret_cast<float4*>(Ws + r * HD + cc * 4) =
                *reinterpret_cast<const float4*>(W + (size_t)(kc * 64 + r) * HD + cc * 4);
        }
        __syncthreads();
#pragma unroll 8
        for (int k = 0; k < 64; k++) {
            float wv[4];
#pragma unroll
            for (int ci = 0; ci < 4; ci++) wv[ci] = Ws[k * HD + ci * 32 + tx];
#pragma unroll
            for (int ri = 0; ri < 16; ri++) {
                float av = As[(ri * 8 + ty) * 64 + k]; // warp-uniform: broadcast
#pragma unroll
                for (int ci = 0; ci < 4; ci++)
                    acc[ri][ci] = fmaf(av, wv[ci], acc[ri][ci]);
            }
        }
        __syncthreads();
    }

#pragma unroll
    for (int ri = 0; ri < 16; ri++) {
        int row = rowBase + ri * 8 + ty;
        if (row < M) {
#pragma unroll
            for (int ci = 0; ci < 4; ci++) {
                int col = ci * 32 + tx;
                float v = acc[ri][ci];
                if (MODE == 1) v = fmaxf(v + bias[col], 0.0f) * mask[row];
                out[(size_t)row * HD + col] = v;
            }
        }
    }
}

// ---------------- fused decoder ----------------
// per block: 128 edges. f[e][k] = zs*zd (k<128) | cs*cd (k>=128)
// hmid = relu(f @ W1 + b1); out = hmid . w2 + b2
__global__ void __launch_bounds__(256)
decode_kernel(const int* __restrict__ pos_e,
              const int* __restrict__ neg_e,
              const float* __restrict__ W1,
              const float* __restrict__ b1,
              const float* __restrict__ w2,
              const float* __restrict__ b2,
              float* __restrict__ out) {
    extern __shared__ float sm[];
    float* fs = sm;           // 128*64
    float* Ws = sm + 8192;    // 64*128
    float* sb1 = sm + 16384;  // 128
    float* sw2 = sm + 16512;  // 128
    int* ssrc = reinterpret_cast<int*>(sm + 16640); // 128
    int* sdst = ssrc + 128;                         // 128

    int tid = threadIdx.x;
    int tx = tid & 31, ty = tid >> 5;
    int tile = blockIdx.x; // 0..6249

    const int* eptr = (tile < NEP / 128) ? pos_e : neg_e;
    int ebase = (tile < NEP / 128) ? tile * 128 : (tile - NEP / 128) * 128;
    if (tid < 128) {
        sb1[tid] = b1[tid];
        sw2[tid] = w2[tid];
        ssrc[tid] = eptr[(ebase + tid) * 2];
        sdst[tid] = eptr[(ebase + tid) * 2 + 1];
    }

    float acc[16][4];
#pragma unroll
    for (int ri = 0; ri < 16; ri++)
#pragma unroll
        for (int ci = 0; ci < 4; ci++) acc[ri][ci] = 0.0f;

    for (int kc = 0; kc < 4; kc++) {
        const float* feat = (kc < 2) ? g_bufB : g_bufD;
        int kofs = (kc & 1) * 64;
        __syncthreads(); // orders ssrc writes (1st iter) / prior compute (later iters)
        // produce f chunk [128][64] from gathered products
#pragma unroll
        for (int i = 0; i < 8; i++) {
            int f4 = tid + 256 * i;
            int e = f4 >> 4, kk = f4 & 15;
            const float4 a = *reinterpret_cast<const float4*>(
                feat + (size_t)ssrc[e] * HD + kofs + kk * 4);
            const float4 d = *reinterpret_cast<const float4*>(
                feat + (size_t)sdst[e] * HD + kofs + kk * 4);
            float4 r = make_float4(a.x * d.x, a.y * d.y, a.z * d.z, a.w * d.w);
            *reinterpret_cast<float4*>(fs + e * 64 + kk * 4) = r;
        }
        // W1 chunk [64][128]
#pragma unroll
        for (int i = 0; i < 8; i++) {
            int f4 = tid + 256 * i;
            int r = f4 >> 5, cc = f4 & 31;
            *reinterpret_cast<float4*>(Ws + r * HD + cc * 4) =
                *reinterpret_cast<const float4*>(W1 + (size_t)(kc * 64 + r) * HD + cc * 4);
        }
        __syncthreads();
#pragma unroll 8
        for (int k = 0; k < 64; k++) {
            float wv[4];
#pragma unroll
            for (int ci = 0; ci < 4; ci++) wv[ci] = Ws[k * HD + ci * 32 + tx];
#pragma unroll
            for (int ri = 0; ri < 16; ri++) {
                float av = fs[(ri * 8 + ty) * 64 + k];
#pragma unroll
                for (int ci = 0; ci < 4; ci++)
                    acc[ri][ci] = fmaf(av, wv[ci], acc[ri][ci]);
            }
        }
    }

    // epilogue: relu + dot with w2, reduce across tx (cols)
    float b2v = b2[0];
    float part[16];
#pragma unroll
    for (int ri = 0; ri < 16; ri++) {
        float p = 0.0f;
#pragma unroll
        for (int ci = 0; ci < 4; ci++) {
            int col = ci * 32 + tx;
            p += fmaxf(acc[ri][ci] + sb1[col], 0.0f) * sw2[col];
        }
        part[ri] = p;
    }
#pragma unroll
    for (int off = 16; off; off >>= 1)
#pragma unroll
        for (int ri = 0; ri < 16; ri++)
            part[ri] += __shfl_xor_sync(0xffffffffu, part[ri], off);
    if (tx == 0) {
#pragma unroll
        for (int ri = 0; ri < 16; ri++)
            out[tile * 128 + ri * 8 + ty] = part[ri] + b2v;
    }
}

// ---------------- host ----------------
extern "C" void kernel_launch(void* const* d_in, const int* in_sizes, int n_in,
                              void* d_out, int out_size) {
    const int*   edge_index  = (const int*)d_in[0];
    const float* chemistry   = (const float*)d_in[1];
    const int*   pos_edge    = (const int*)d_in[2];
    const int*   neg_edge    = (const int*)d_in[3];
    const float* smiles_mask = (const float*)d_in[4];
    const float* node_emb    = (const float*)d_in[5];
    const float* conv_w      = (const float*)d_in[6];
    const float* conv_b      = (const float*)d_in[7];
    const float* chem_w      = (const float*)d_in[8];
    const float* chem_b      = (const float*)d_in[9];
    const float* dec_w1      = (const float*)d_in[10];
    const float* dec_b1      = (const float*)d_in[11];
    const float* dec_w2      = (const float*)d_in[12];
    const float* dec_b2      = (const float*)d_in[13];
    float* out = (float*)d_out;

    void *pA, *pB, *pC, *pD, *pdeg;
    cudaGetSymbolAddress(&pA, g_bufA);
    cudaGetSymbolAddress(&pB, g_bufB);
    cudaGetSymbolAddress(&pC, g_bufC);
    cudaGetSymbolAddress(&pD, g_bufD);
    cudaGetSymbolAddress(&pdeg, g_deg);

    const int GEMM_SMEM = (128 * 64 + 64 * 128) * 4;               // 65536
    const int DEC_SMEM  = (8192 + 8192 + 128 + 128) * 4 + 256 * 4; // 67584
    cudaFuncSetAttribute(gemm128_kernel<128, 0>,
                         cudaFuncAttributeMaxDynamicSharedMemorySize, GEMM_SMEM);
    cudaFuncSetAttribute(gemm128_kernel<768, 1>,
                         cudaFuncAttributeMaxDynamicSharedMemorySize, GEMM_SMEM);
    cudaFuncSetAttribute(decode_kernel,
                         cudaFuncAttributeMaxDynamicSharedMemorySize, DEC_SMEM);

    const int MBLK = (NN + 127) / 128; // 391

    // degrees
    cudaMemsetAsync(pdeg, 0, NN * sizeof(int), 0);
    deg_kernel<<<(NE + 255) / 256, 256>>>(edge_index + NE);
    dinv_kernel<<<(NN + 255) / 256, 256>>>();

    // layer 0
    gemm128_kernel<128, 0><<<MBLK, 256, GEMM_SMEM>>>(node_emb, conv_w, nullptr, nullptr,
                                                     (float*)pA, NN);
    cudaMemsetAsync(pC, 0, (size_t)NN * HD * sizeof(float), 0);
    scatter_kernel<<<(NE * 32 + 255) / 256, 256>>>(edge_index, (float*)pA, (float*)pC);
    bias_relu_kernel<<<(NN * HD + 255) / 256, 256>>>((float*)pC, conv_b, (float*)pB);

    // layer 1
    gemm128_kernel<128, 0><<<MBLK, 256, GEMM_SMEM>>>((const float*)pB, conv_w + HD * HD,
                                                     nullptr, nullptr, (float*)pA, NN);
    cudaMemsetAsync(pC, 0, (size_t)NN * HD * sizeof(float), 0);
    scatter_kernel<<<(NE * 32 + 255) / 256, 256>>>(edge_index, (float*)pA, (float*)pC);
    bias_relu_kernel<<<(NN * HD + 255) / 256, 256>>>((float*)pC, conv_b + HD, (float*)pB);

    // chemistry MLP: c = relu(chem @ W + b) * mask
    gemm128_kernel<768, 1><<<MBLK, 256, GEMM_SMEM>>>(chemistry, chem_w, chem_b,
                                                     smiles_mask, (float*)pD, NN);

    // decoder: 3125 pos tiles + 3125 neg tiles
    decode_kernel<<<2 * NEP / 128, 256, DEC_SMEM>>>(pos_edge, neg_edge, dec_w1, dec_b1,
                                                    dec_w2, dec_b2, out);
}

// round 3
// speedup vs baseline: 1.6163x; 1.6163x over previous
#include <cuda_runtime.h>

#define NN 50000
#define NE 1000000
#define NEP 400000
#define HD 128
#define CD 768

// ---------------- scratch (no allocation allowed) ----------------
static __device__ float g_bufA[NN * HD]; // h = z @ W
static __device__ float g_bufB[NN * HD]; // z (post-layer)
static __device__ float g_bufC[NN * HD]; // agg
static __device__ float g_bufD[NN * HD]; // c (chem features)
static __device__ float g_dinv[NN];
static __device__ int   g_deg[NN];

// packed f32x2 helpers (Blackwell FFMA2 path)
__device__ __forceinline__ unsigned long long pack2(float lo, float hi) {
    unsigned long long r;
    asm("mov.b64 %0, {%1, %2};" : "=l"(r) : "f"(lo), "f"(hi));
    return r;
}
__device__ __forceinline__ unsigned long long pack2rep(float v) {
    unsigned long long r;
    asm("mov.b64 %0, {%1, %1};" : "=l"(r) : "f"(v));
    return r;
}
__device__ __forceinline__ void fma2(unsigned long long& acc,
                                     unsigned long long a,
                                     unsigned long long b) {
    asm("fma.rn.f32x2 %0, %1, %2, %0;" : "+l"(acc) : "l"(a), "l"(b));
}
__device__ __forceinline__ void unpack2(unsigned long long v, float& lo, float& hi) {
    asm("mov.b64 {%0, %1}, %2;" : "=f"(lo), "=f"(hi) : "l"(v));
}

#define AT_STRIDE 130  // padded transposed-tile stride (words), kills bank conflicts

// ---------------- degree / dinv ----------------
__global__ void deg_kernel(const int* __restrict__ col) {
    int e = blockIdx.x * blockDim.x + threadIdx.x;
    if (e < NE) atomicAdd(&g_deg[col[e]], 1);
}

__global__ void dinv_kernel() {
    int n = blockIdx.x * blockDim.x + threadIdx.x;
    if (n < NN) {
        int d = g_deg[n];
        g_dinv[n] = d > 0 ? rsqrtf((float)d) : 0.0f;
    }
}

// ---------------- edge scatter: agg[col] += h[row] * norm ----------------
// one warp per edge; lane handles 4 contiguous features; single red.v4 per lane
__global__ void scatter_kernel(const int* __restrict__ ei,
                               const float* __restrict__ h,
                               float* __restrict__ agg) {
    int gt = blockIdx.x * blockDim.x + threadIdx.x;
    int e = gt >> 5;
    int lane = gt & 31;
    if (e >= NE) return;
    int r = ei[e];
    int c = ei[NE + e];
    float nrm = g_dinv[r] * g_dinv[c];
    float4 v = reinterpret_cast<const float4*>(h)[r * 32 + lane];
    float* dst = agg + (size_t)c * HD + lane * 4;
    asm volatile("red.global.add.v4.f32 [%0], {%1, %2, %3, %4};"
                 :: "l"(dst), "f"(v.x * nrm), "f"(v.y * nrm),
                    "f"(v.z * nrm), "f"(v.w * nrm)
                 : "memory");
}

// ---------------- z = relu(agg + b) ----------------
__global__ void bias_relu_kernel(const float* __restrict__ agg,
                                 const float* __restrict__ b,
                                 float* __restrict__ z) {
    int i = blockIdx.x * blockDim.x + threadIdx.x;
    if (i < NN * HD) z[i] = fmaxf(agg[i] + b[i & (HD - 1)], 0.0f);
}

// ---------------- tiled fp32 GEMM (FFMA2): out = op(A[M,K] @ W[K,128]) -------
// tile 128 rows x 128 cols, K chunked by 64. 256 threads.
// A chunk stored TRANSPOSED in smem: As_T[k][row], stride AT_STRIDE.
// Each thread: 8 row-pairs (ty*16 + 2*r2) x 4 cols (ci*32+tx), acc in f32x2.
// MODE 0: raw store. MODE 1: relu(x + bias[col]) * mask[row]
template <int KTOT, int MODE>
__global__ void __launch_bounds__(256)
gemm128_kernel(const float* __restrict__ A,
               const float* __restrict__ W,
               const float* __restrict__ bias,
               const float* __restrict__ mask,
               float* __restrict__ out, int M) {
    extern __shared__ float sm[];
    float* AsT = sm;                   // 64 * 130
    float* Ws  = sm + 64 * AT_STRIDE;  // 64 * 128
    int tid = threadIdx.x;
    int tx = tid & 31, ty = tid >> 5;
    int rowBase = blockIdx.x * 128;

    unsigned long long acc2[8][4];
#pragma unroll
    for (int r2 = 0; r2 < 8; r2++)
#pragma unroll
        for (int ci = 0; ci < 4; ci++) acc2[r2][ci] = 0ull;

    for (int kc = 0; kc < KTOT / 64; kc++) {
        // load A chunk, store transposed [64 k][128 row]
#pragma unroll
        for (int i = 0; i < 8; i++) {
            int f4 = tid + 256 * i;       // 0..2047
            int r = f4 >> 4, kk = f4 & 15;
            int gr = rowBase + r;
            float4 v = make_float4(0.f, 0.f, 0.f, 0.f);
            if (gr < M)
                v = *reinterpret_cast<const float4*>(A + (size_t)gr * KTOT + kc * 64 + kk * 4);
            AsT[(kk * 4 + 0) * AT_STRIDE + r] = v.x;
            AsT[(kk * 4 + 1) * AT_STRIDE + r] = v.y;
            AsT[(kk * 4 + 2) * AT_STRIDE + r] = v.z;
            AsT[(kk * 4 + 3) * AT_STRIDE + r] = v.w;
        }
        // load W chunk [64][128]
#pragma unroll
        for (int i = 0; i < 8; i++) {
            int f4 = tid + 256 * i;
            int r = f4 >> 5, cc = f4 & 31;
            *reinterpret_cast<float4*>(Ws + r * HD + cc * 4) =
                *reinterpret_cast<const float4*>(W + (size_t)(kc * 64 + r) * HD + cc * 4);
        }
        __syncthreads();
#pragma unroll 4
        for (int k = 0; k < 64; k++) {
            unsigned long long w2[4];
#pragma unroll
            for (int ci = 0; ci < 4; ci++)
                w2[ci] = pack2rep(Ws[k * HD + ci * 32 + tx]);
            const float* arow = AsT + k * AT_STRIDE + ty * 16;
#pragma unroll
            for (int r2 = 0; r2 < 8; r2++) {
                float2 a = *reinterpret_cast<const float2*>(arow + 2 * r2);
                unsigned long long a2 = pack2(a.x, a.y);
#pragma unroll
                for (int ci = 0; ci < 4; ci++) fma2(acc2[r2][ci], a2, w2[ci]);
            }
        }
        __syncthreads();
    }

#pragma unroll
    for (int r2 = 0; r2 < 8; r2++) {
        int row0 = rowBase + ty * 16 + 2 * r2;
#pragma unroll
        for (int ci = 0; ci < 4; ci++) {
            int col = ci * 32 + tx;
            float lo, hi;
            unpack2(acc2[r2][ci], lo, hi);
            if (MODE == 1) {
                lo = fmaxf(lo + bias[col], 0.0f);
                hi = fmaxf(hi + bias[col], 0.0f);
            }
            if (row0 < M) {
                float v = (MODE == 1) ? lo * mask[row0] : lo;
                out[(size_t)row0 * HD + col] = v;
            }
            if (row0 + 1 < M) {
                float v = (MODE == 1) ? hi * mask[row0 + 1] : hi;
                out[(size_t)(row0 + 1) * HD + col] = v;
            }
        }
    }
}

// ---------------- fused decoder (FFMA2) ----------------
// per block: 128 edges. f[e][k] = zs*zd (k<128) | cs*cd (k>=128)
// f chunk stored TRANSPOSED: fsT[k][e]. hmid = relu(f@W1+b1); out = hmid.w2+b2
__global__ void __launch_bounds__(256)
decode_kernel(const int* __restrict__ pos_e,
              const int* __restrict__ neg_e,
              const float* __restrict__ W1,
              const float* __restrict__ b1,
              const float* __restrict__ w2,
              const float* __restrict__ b2,
              float* __restrict__ out) {
    extern __shared__ float sm[];
    float* fsT = sm;                        // 64*130 = 8320
    float* Ws  = sm + 64 * AT_STRIDE;       // 8192
    float* sb1 = sm + 64 * AT_STRIDE + 8192;       // 128
    float* sw2 = sb1 + 128;                        // 128
    int* ssrc = reinterpret_cast<int*>(sw2 + 128); // 128
    int* sdst = ssrc + 128;                        // 128

    int tid = threadIdx.x;
    int tx = tid & 31, ty = tid >> 5;
    int tile = blockIdx.x; // 0..6249

    const int* eptr = (tile < NEP / 128) ? pos_e : neg_e;
    int ebase = (tile < NEP / 128) ? tile * 128 : (tile - NEP / 128) * 128;
    if (tid < 128) {
        sb1[tid] = b1[tid];
        sw2[tid] = w2[tid];
        ssrc[tid] = eptr[(ebase + tid) * 2];
        sdst[tid] = eptr[(ebase + tid) * 2 + 1];
    }

    unsigned long long acc2[8][4];
#pragma unroll
    for (int r2 = 0; r2 < 8; r2++)
#pragma unroll
        for (int ci = 0; ci < 4; ci++) acc2[r2][ci] = 0ull;

    for (int kc = 0; kc < 4; kc++) {
        const float* feat = (kc < 2) ? g_bufB : g_bufD;
        int kofs = (kc & 1) * 64;
        __syncthreads(); // orders ssrc writes (1st iter) / prior compute (later iters)
        // produce f chunk, store transposed [64 k][128 e]
#pragma unroll
        for (int i = 0; i < 8; i++) {
            int f4 = tid + 256 * i;
            int e = f4 >> 4, kk = f4 & 15;
            const float4 a = *reinterpret_cast<const float4*>(
                feat + (size_t)ssrc[e] * HD + kofs + kk * 4);
            const float4 d = *reinterpret_cast<const float4*>(
                feat + (size_t)sdst[e] * HD + kofs + kk * 4);
            fsT[(kk * 4 + 0) * AT_STRIDE + e] = a.x * d.x;
            fsT[(kk * 4 + 1) * AT_STRIDE + e] = a.y * d.y;
            fsT[(kk * 4 + 2) * AT_STRIDE + e] = a.z * d.z;
            fsT[(kk * 4 + 3) * AT_STRIDE + e] = a.w * d.w;
        }
        // W1 chunk [64][128]
#pragma unroll
        for (int i = 0; i < 8; i++) {
            int f4 = tid + 256 * i;
            int r = f4 >> 5, cc = f4 & 31;
            *reinterpret_cast<float4*>(Ws + r * HD + cc * 4) =
                *reinterpret_cast<const float4*>(W1 + (size_t)(kc * 64 + r) * HD + cc * 4);
        }
        __syncthreads();
#pragma unroll 4
        for (int k = 0; k < 64; k++) {
            unsigned long long w2v[4];
#pragma unroll
            for (int ci = 0; ci < 4; ci++)
                w2v[ci] = pack2rep(Ws[k * HD + ci * 32 + tx]);
            const float* arow = fsT + k * AT_STRIDE + ty * 16;
#pragma unroll
            for (int r2 = 0; r2 < 8; r2++) {
                float2 a = *reinterpret_cast<const float2*>(arow + 2 * r2);
                unsigned long long a2 = pack2(a.x, a.y);
#pragma unroll
                for (int ci = 0; ci < 4; ci++) fma2(acc2[r2][ci], a2, w2v[ci]);
            }
        }
    }

    // epilogue: relu + dot with w2, reduce across tx (cols)
    float b2v = b2[0];
    float part[16];
#pragma unroll
    for (int r2 = 0; r2 < 8; r2++) {
        float plo = 0.0f, phi = 0.0f;
#pragma unroll
        for (int ci = 0; ci < 4; ci++) {
            int col = ci * 32 + tx;
            float lo, hi;
            unpack2(acc2[r2][ci], lo, hi);
            plo += fmaxf(lo + sb1[col], 0.0f) * sw2[col];
            phi += fmaxf(hi + sb1[col], 0.0f) * sw2[col];
        }
        part[2 * r2] = plo;
        part[2 * r2 + 1] = phi;
    }
#pragma unroll
    for (int off = 16; off; off >>= 1)
#pragma unroll
        for (int ri = 0; ri < 16; ri++)
            part[ri] += __shfl_xor_sync(0xffffffffu, part[ri], off);
    if (tx == 0) {
#pragma unroll
        for (int ri = 0; ri < 16; ri++)
            out[tile * 128 + ty * 16 + ri] = part[ri] + b2v;
    }
}

// ---------------- host ----------------
extern "C" void kernel_launch(void* const* d_in, const int* in_sizes, int n_in,
                              void* d_out, int out_size) {
    const int*   edge_index  = (const int*)d_in[0];
    const float* chemistry   = (const float*)d_in[1];
    const int*   pos_edge    = (const int*)d_in[2];
    const int*   neg_edge    = (const int*)d_in[3];
    const float* smiles_mask = (const float*)d_in[4];
    const float* node_emb    = (const float*)d_in[5];
    const float* conv_w      = (const float*)d_in[6];
    const float* conv_b      = (const float*)d_in[7];
    const float* chem_w      = (const float*)d_in[8];
    const float* chem_b      = (const float*)d_in[9];
    const float* dec_w1      = (const float*)d_in[10];
    const float* dec_b1      = (const float*)d_in[11];
    const float* dec_w2      = (const float*)d_in[12];
    const float* dec_b2      = (const float*)d_in[13];
    float* out = (float*)d_out;

    void *pA, *pB, *pC, *pD, *pdeg;
    cudaGetSymbolAddress(&pA, g_bufA);
    cudaGetSymbolAddress(&pB, g_bufB);
    cudaGetSymbolAddress(&pC, g_bufC);
    cudaGetSymbolAddress(&pD, g_bufD);
    cudaGetSymbolAddress(&pdeg, g_deg);

    const int GEMM_SMEM = (64 * AT_STRIDE + 64 * 128) * 4;               // 66048
    const int DEC_SMEM  = (64 * AT_STRIDE + 64 * 128 + 256) * 4 + 1024;  // 68096
    cudaFuncSetAttribute(gemm128_kernel<128, 0>,
                         cudaFuncAttributeMaxDynamicSharedMemorySize, GEMM_SMEM);
    cudaFuncSetAttribute(gemm128_kernel<768, 1>,
                         cudaFuncAttributeMaxDynamicSharedMemorySize, GEMM_SMEM);
    cudaFuncSetAttribute(decode_kernel,
                         cudaFuncAttributeMaxDynamicSharedMemorySize, DEC_SMEM);

    const int MBLK = (NN + 127) / 128; // 391

    // degrees
    cudaMemsetAsync(pdeg, 0, NN * sizeof(int), 0);
    deg_kernel<<<(NE + 255) / 256, 256>>>(edge_index + NE);
    dinv_kernel<<<(NN + 255) / 256, 256>>>();

    // layer 0
    gemm128_kernel<128, 0><<<MBLK, 256, GEMM_SMEM>>>(node_emb, conv_w, nullptr, nullptr,
                                                     (float*)pA, NN);
    cudaMemsetAsync(pC, 0, (size_t)NN * HD * sizeof(float), 0);
    scatter_kernel<<<(NE * 32 + 255) / 256, 256>>>(edge_index, (float*)pA, (float*)pC);
    bias_relu_kernel<<<(NN * HD + 255) / 256, 256>>>((float*)pC, conv_b, (float*)pB);

    // layer 1
    gemm128_kernel<128, 0><<<MBLK, 256, GEMM_SMEM>>>((const float*)pB, conv_w + HD * HD,
                                                     nullptr, nullptr, (float*)pA, NN);
    cudaMemsetAsync(pC, 0, (size_t)NN * HD * sizeof(float), 0);
    scatter_kernel<<<(NE * 32 + 255) / 256, 256>>>(edge_index, (float*)pA, (float*)pC);
    bias_relu_kernel<<<(NN * HD + 255) / 256, 256>>>((float*)pC, conv_b + HD, (float*)pB);

    // chemistry MLP: c = relu(chem @ W + b) * mask
    gemm128_kernel<768, 1><<<MBLK, 256, GEMM_SMEM>>>(chemistry, chem_w, chem_b,
                                                     smiles_mask, (float*)pD, NN);

    // decoder: 3125 pos tiles + 3125 neg tiles
    decode_kernel<<<2 * NEP / 128, 256, DEC_SMEM>>>(pos_edge, neg_edge, dec_w1, dec_b1,
                                                    dec_w2, dec_b2, out);
}